// round 9
// baseline (speedup 1.0000x reference)
#include <cuda_runtime.h>
#include <cuda_bf16.h>
#include <cstdint>

// Problem constants (fixed by the reference)
#define H 64
#define V 128
#define S 64
#define BATCH 256
#define L 4096

typedef unsigned long long u64;
typedef unsigned int u32;
typedef unsigned short u16;

// Scratch (no allocs allowed)
__device__ float d_hn[V * H];   // LN'd hidden per vocab id
// A-fragment table: [s=64][p=64] u64 words = {hi_u32{g[2p],g[2p+1]}, lo_u32{...}}
__device__ u64 d_gT64[S * (V / 2)];

__device__ __forceinline__ void mma_bf16(float* c, u32 a0, u32 a1, u32 a2, u32 a3,
                                         u32 b0, u32 b1) {
    asm volatile(
        "mma.sync.aligned.m16n8k16.row.col.f32.bf16.bf16.f32 "
        "{%0,%1,%2,%3}, {%4,%5,%6,%7}, {%8,%9}, {%0,%1,%2,%3};"
        : "+f"(c[0]), "+f"(c[1]), "+f"(c[2]), "+f"(c[3])
        : "r"(a0), "r"(a1), "r"(a2), "r"(a3), "r"(b0), "r"(b1));
}

// ---------------------------------------------------------------------------
// Kernel 1: per-vocab precompute (writes d_hn + A-fragment table).
// grid = V, 128 threads.
// ---------------------------------------------------------------------------
__global__ void __launch_bounds__(128) prep_kernel(
        const float* __restrict__ embed_w,
        const float* __restrict__ w1,
        const float* __restrict__ b1,
        const float* __restrict__ w2,
        const float* __restrict__ b2,
        const float* __restrict__ ln_g,
        const float* __restrict__ ln_b,
        const float* __restrict__ gate_w,
        const float* __restrict__ gate_b) {
    int t = threadIdx.x;    // 0..127
    int lane = t & 31;
    int warp = t >> 5;
    int v = blockIdx.x;

    __shared__ float hs[H];
    __shared__ float us[2 * H];
    __shared__ float hns[H];
    __shared__ float wred[2][2];

    if (t < H) hs[t] = embed_w[v * H + t];
    __syncthreads();

    // u = relu(h @ w1 + b1): 128 outputs, one per thread
    {
        float acc = b1[t];
#pragma unroll
        for (int k = 0; k < H; k++) acc = fmaf(hs[k], w1[k * (2 * H) + t], acc);
        us[t] = fmaxf(acc, 0.0f);
    }
    __syncthreads();

    float xval = 0.0f;
    if (t < H) {
        float acc = b2[t];
#pragma unroll
        for (int k = 0; k < 2 * H; k++) acc = fmaf(us[k], w2[k * H + t], acc);
        xval = hs[t] + acc;
        float s = xval, sq = xval * xval;
#pragma unroll
        for (int off = 16; off > 0; off >>= 1) {
            s  += __shfl_xor_sync(0xffffffffu, s, off);
            sq += __shfl_xor_sync(0xffffffffu, sq, off);
        }
        if (lane == 0) { wred[warp][0] = s; wred[warp][1] = sq; }
    }
    __syncthreads();

    if (t < H) {
        float s  = wred[0][0] + wred[1][0];
        float sq = wred[0][1] + wred[1][1];
        float mu = s * (1.0f / H);
        float var = sq * (1.0f / H) - mu * mu;
        float rstd = rsqrtf(var + 1e-5f);
        float val = (xval - mu) * rstd * ln_g[t] + ln_b[t];
        hns[t] = val;
        d_hn[v * H + t] = val;
    }
    __syncthreads();

    // gate softmax over S=64 (threads 0..63) + scatter into A-frag table
    if (t < S) {
        float l = gate_b[t];
#pragma unroll
        for (int k = 0; k < H; k++) l = fmaf(hns[k], gate_w[k * S + t], l);
        float m = l;
#pragma unroll
        for (int off = 16; off > 0; off >>= 1)
            m = fmaxf(m, __shfl_xor_sync(0xffffffffu, m, off));
        if (lane == 0) wred[warp][0] = m;
        __syncthreads();
        m = fmaxf(wred[0][0], wred[1][0]);
        float e = expf(l - m);
        float ssum = e;
#pragma unroll
        for (int off = 16; off > 0; off >>= 1)
            ssum += __shfl_xor_sync(0xffffffffu, ssum, off);
        if (lane == 0) wred[warp][1] = ssum;
        __syncthreads();
        float gv = e / (wred[0][1] + wred[1][1]);

        // A[s=t][k=v]: hi/lo bf16 into d_gT64[s*64 + v/2] halves
        __nv_bfloat16 hi = __float2bfloat16(gv);
        __nv_bfloat16 lo = __float2bfloat16(gv - __bfloat162float(hi));
        int s = t, p = v >> 1, e2 = v & 1;
        u16* q = (u16*)d_gT64;
        q[(s * 64 + p) * 4 + e2]     = *(u16*)&hi;
        q[(s * 64 + p) * 4 + 2 + e2] = *(u16*)&lo;
    } else {
        __syncthreads();
        __syncthreads();
    }
}

// ---------------------------------------------------------------------------
// Kernel 2 (HMMA): one batch per block, 256 threads = 8 warps.
// Phase 0: in-block histogram of seq[b, 0:L-1].
// Phase 1: B build (bf16 hi/lo of cnt (.) HN).
// Phase 2: MMA — warp (wm = w&3) owns m16 rows, (wn = w>>2) owns n-half.
// Phase 3: cosine attention tail + output GEMV.
// ---------------------------------------------------------------------------
#define BPAD 68

struct FinalSmem {
    union {
        int sub[8][V];          // 4 KB (phase 0)
        u64 dummy_align;
    } h;
    u64 Bint[64 * BPAD];        // 34816 B
    float skeys[S][H + 1];      // 16640 B
    float cs[V];
    float sq[H];
    float sattn[S];
    float sctx[H];
    float wA[2], wB2[2], wC[2];
};

__global__ void __launch_bounds__(256, 2) final_kernel(
        const int* __restrict__ seq,
        const float* __restrict__ slot_keys,
        const float* __restrict__ out_w,
        const float* __restrict__ out_b,
        float* __restrict__ out) {
    extern __shared__ char smraw[];
    FinalSmem* sm = (FinalSmem*)smraw;

    int b = blockIdx.x;
    int t = threadIdx.x;   // 0..255
    int lane = t & 31;
    int warp = t >> 5;     // 0..7
    int gid = lane >> 2;   // 0..7
    int tig = lane & 3;    // 0..3

    // ---- Phase 0: histogram of seq[b, 0:4095] ----
    for (int i = t; i < 8 * V; i += 256) ((int*)sm->h.sub)[i] = 0;
    __syncthreads();
    {
        const int4* s4 = (const int4*)(seq + b * L);
        for (int i = t; i < 1023; i += 256) {
            int4 x = s4[i];
            atomicAdd(&sm->h.sub[warp][x.x], 1);
            atomicAdd(&sm->h.sub[warp][x.y], 1);
            atomicAdd(&sm->h.sub[warp][x.z], 1);
            atomicAdd(&sm->h.sub[warp][x.w], 1);
        }
        if (t < 3) atomicAdd(&sm->h.sub[warp][seq[b * L + 4092 + t]], 1);
    }
    __syncthreads();
    if (t < V) {
        int tot = 0;
#pragma unroll
        for (int k = 0; k < 8; k++) tot += sm->h.sub[k][t];
        sm->cs[t] = (float)tot;
    }
    __syncthreads();

    // ---- Phase 1: B build ----
#pragma unroll
    for (int idx = t; idx < 64 * 64; idx += 256) {
        int p = idx >> 6, h = idx & 63;
        float x0 = d_hn[(2 * p) * H + h] * sm->cs[2 * p];
        float x1 = d_hn[(2 * p + 1) * H + h] * sm->cs[2 * p + 1];
        __nv_bfloat16 h0 = __float2bfloat16(x0);
        __nv_bfloat16 h1 = __float2bfloat16(x1);
        __nv_bfloat16 l0 = __float2bfloat16(x0 - __bfloat162float(h0));
        __nv_bfloat16 l1 = __float2bfloat16(x1 - __bfloat162float(h1));
        __nv_bfloat162 hp; hp.x = h0; hp.y = h1;
        __nv_bfloat162 lp; lp.x = l0; lp.y = l1;
        u64 w = (u64)(*(u32*)&hp) | ((u64)(*(u32*)&lp) << 32);
        sm->Bint[p * BPAD + h] = w;
    }
    __syncthreads();

    // ---- Phase 2: MMA ----
    const int wm = warp & 3;       // m-tile
    const int wn = warp >> 2;      // n-half
    float acc[4][4];
#pragma unroll
    for (int nt = 0; nt < 4; nt++)
#pragma unroll
        for (int i = 0; i < 4; i++) acc[nt][i] = 0.0f;

    const int row0 = wm * 16 + gid;
#pragma unroll
    for (int kt = 0; kt < 8; kt++) {
        int pb = kt * 8 + tig;
        u64 A0 = d_gT64[row0 * 64 + pb];
        u64 A1 = d_gT64[(row0 + 8) * 64 + pb];
        u64 A2 = d_gT64[row0 * 64 + pb + 4];
        u64 A3 = d_gT64[(row0 + 8) * 64 + pb + 4];
        u32 aH0 = (u32)A0, aL0 = (u32)(A0 >> 32);
        u32 aH1 = (u32)A1, aL1 = (u32)(A1 >> 32);
        u32 aH2 = (u32)A2, aL2 = (u32)(A2 >> 32);
        u32 aH3 = (u32)A3, aL3 = (u32)(A3 >> 32);
#pragma unroll
        for (int nt = 0; nt < 4; nt++) {
            int h = (wn * 4 + nt) * 8 + gid;
            u64 B0 = sm->Bint[pb * BPAD + h];
            u64 B1 = sm->Bint[(pb + 4) * BPAD + h];
            u32 bH0 = (u32)B0, bL0 = (u32)(B0 >> 32);
            u32 bH1 = (u32)B1, bL1 = (u32)(B1 >> 32);
            mma_bf16(acc[nt], aH0, aH1, aH2, aH3, bH0, bH1);
            mma_bf16(acc[nt], aH0, aH1, aH2, aH3, bL0, bL1);
            mma_bf16(acc[nt], aL0, aL1, aL2, aL3, bH0, bH1);
        }
    }

    // ---- Phase 3: keys (+ slot_keys) -> shared ----
#pragma unroll
    for (int nt = 0; nt < 4; nt++) {
        int col = (wn * 4 + nt) * 8 + tig * 2;
        sm->skeys[row0][col]         = acc[nt][0] + slot_keys[row0 * H + col];
        sm->skeys[row0][col + 1]     = acc[nt][1] + slot_keys[row0 * H + col + 1];
        sm->skeys[row0 + 8][col]     = acc[nt][2] + slot_keys[(row0 + 8) * H + col];
        sm->skeys[row0 + 8][col + 1] = acc[nt][3] + slot_keys[(row0 + 8) * H + col + 1];
    }

    // q = hn[last token]; q norm (warps 0,1)
    int qi = seq[b * L + (L - 1)];
    if (t < H) {
        float qv = d_hn[qi * H + t];
        sm->sq[t] = qv;
        float s = qv * qv;
#pragma unroll
        for (int off = 16; off > 0; off >>= 1)
            s += __shfl_xor_sync(0xffffffffu, s, off);
        if (lane == 0) sm->wA[warp] = s;
    }
    __syncthreads();

    float simv = 0.0f;
    if (t < S) {
        float qinv = rsqrtf(fmaxf(sm->wA[0] + sm->wA[1], 1e-24f));
        float dot = 0.0f, nk = 0.0f;
#pragma unroll
        for (int k = 0; k < H; k++) {
            float kv = sm->skeys[t][k];
            dot = fmaf(kv, sm->sq[k], dot);
            nk = fmaf(kv, kv, nk);
        }
        simv = dot * qinv / fmaxf(sqrtf(nk), 1e-12f);
        float m = simv;
#pragma unroll
        for (int off = 16; off > 0; off >>= 1)
            m = fmaxf(m, __shfl_xor_sync(0xffffffffu, m, off));
        if (lane == 0) sm->wB2[warp] = m;
    }
    __syncthreads();

    float ev = 0.0f;
    if (t < S) {
        float m = fmaxf(sm->wB2[0], sm->wB2[1]);
        ev = expf(simv - m);
        float s = ev;
#pragma unroll
        for (int off = 16; off > 0; off >>= 1)
            s += __shfl_xor_sync(0xffffffffu, s, off);
        if (lane == 0) sm->wC[warp] = s;
    }
    __syncthreads();

    if (t < S) sm->sattn[t] = ev / (sm->wC[0] + sm->wC[1]);
    __syncthreads();

    if (t < H) {
        float c = 0.0f;
#pragma unroll
        for (int n = 0; n < S; n++) c = fmaf(sm->sattn[n], sm->skeys[n][t], c);
        sm->sctx[t] = c;
    }
    __syncthreads();

    // out[b, j] = ctx @ out_w + out_b (threads 0..127, 1 column each)
    if (t < V) {
        float o = out_b[t];
#pragma unroll
        for (int k = 0; k < H; k++) o = fmaf(sm->sctx[k], out_w[k * V + t], o);
        out[b * V + t] = o;
    }
}

// ---------------------------------------------------------------------------
extern "C" void kernel_launch(void* const* d_in, const int* in_sizes, int n_in,
                              void* d_out, int out_size) {
    const int*   seq       = (const int*)d_in[0];
    const float* embed_w   = (const float*)d_in[1];
    const float* w1        = (const float*)d_in[2];
    const float* b1        = (const float*)d_in[3];
    const float* w2        = (const float*)d_in[4];
    const float* b2        = (const float*)d_in[5];
    const float* ln_g      = (const float*)d_in[6];
    const float* ln_b      = (const float*)d_in[7];
    const float* slot_keys = (const float*)d_in[8];
    // d_in[9] = slot_vals (unused: reference sets vals = keys)
    const float* gate_w    = (const float*)d_in[10];
    const float* gate_b    = (const float*)d_in[11];
    const float* out_w     = (const float*)d_in[12];
    const float* out_b     = (const float*)d_in[13];
    float* out = (float*)d_out;

    int smem_bytes = (int)sizeof(FinalSmem);
    cudaFuncSetAttribute(final_kernel,
                         cudaFuncAttributeMaxDynamicSharedMemorySize, smem_bytes);

    prep_kernel<<<V, 128>>>(embed_w, w1, b1, w2, b2, ln_g, ln_b, gate_w, gate_b);
    final_kernel<<<BATCH, 256, smem_bytes>>>(seq, slot_keys, out_w, out_b, out);
}